// round 1
// baseline (speedup 1.0000x reference)
#include <cuda_runtime.h>
#include <math.h>

#define BB 16
#define HH 50
#define SS 256
#define DD 256
#define KK 32
#define SM1 255           // S-1 candidate rows
#define FULL 0xFFFFFFFFu

// Output layout (tuple flattened, all float32):
//  [0, PS_N)                    ps_terms  (B, H*K, D)
//  [PS_N, PS_N+MK_N)            ps_term_mask (B, H*K)
//  [PS_N+MK_N, PS_N+2*MK_N)     kid (B, H, K) cast to float
#define PS_N   (BB*HH*KK*DD)     // 6,553,600
#define MK_N   (BB*HH*KK)        // 25,600

__device__ float d_qn[BB * DD];  // normalized user_repr scratch

// ---------------------------------------------------------------------------
// Kernel 1: normalize user_repr per batch. 16 blocks x 256 threads.
// ---------------------------------------------------------------------------
__global__ __launch_bounds__(256) void qn_kernel(const float* __restrict__ user)
{
    int b = blockIdx.x;
    int tid = threadIdx.x;
    int lane = tid & 31, warp = tid >> 5;

    float v = user[b * DD + tid];
    float ss = v * v;
    #pragma unroll
    for (int off = 16; off; off >>= 1) ss += __shfl_xor_sync(FULL, ss, off);

    __shared__ float wsum[8];
    __shared__ float norm_s;
    if (lane == 0) wsum[warp] = ss;
    __syncthreads();
    if (tid == 0) {
        float t = 0.f;
        #pragma unroll
        for (int i = 0; i < 8; i++) t += wsum[i];
        norm_s = fmaxf(sqrtf(t), 1e-12f);
    }
    __syncthreads();
    d_qn[b * DD + tid] = v / norm_s;
}

// ---------------------------------------------------------------------------
// Kernel 2: one CTA per (b,h). 256 threads = 8 warps.
//   Phase A: warp-per-row cosine scores (255 rows), masked, -> SMEM
//   Phase B: warp 0 iterative argmax top-32 (tie-break: smaller index),
//            softmax, emit mask + kid
//   Phase C: all warps: weighted gather of news_embedding + segment bias
// ---------------------------------------------------------------------------
__global__ __launch_bounds__(256) void matching_reducer_kernel(
    const float* __restrict__ nse,   // news_selection_embedding (B,H,S,D)
    const float* __restrict__ ne,    // news_embedding           (B,H,S,D)
    const float* __restrict__ am,    // his_attn_mask            (B,H,S)
    const int*   __restrict__ rm,    // his_refined_mask         (B,H,S)
    const float* __restrict__ seg,   // segment_embedding        (H,1,D)
    float*       __restrict__ out)
{
    const int bh = blockIdx.x;       // 0..799
    const int b  = bh / HH;
    const int h  = bh - b * HH;
    const int tid  = threadIdx.x;
    const int lane = tid & 31;
    const int warp = tid >> 5;

    __shared__ float sh_q[DD];
    __shared__ float sh_seg[DD];
    __shared__ float sh_sc[256];
    __shared__ float sh_tv[KK];
    __shared__ int   sh_ti[KK];
    __shared__ float sh_w[KK];

    if (tid < 64) {
        ((float4*)sh_q)[tid]   = ((const float4*)(d_qn + b * DD))[tid];
        ((float4*)sh_seg)[tid] = ((const float4*)(seg + h * DD))[tid];
    }
    if (tid == 0) sh_sc[255] = -INFINITY;   // sentinel (slot 255 has no row)
    __syncthreads();

    float qr[8];
    #pragma unroll
    for (int j = 0; j < 8; j++) qr[j] = sh_q[lane * 8 + j];

    const float* selbase = nse + ((size_t)bh * SS + 1) * DD;
    const int*   rmb     = rm  + (size_t)bh * SS + 1;

    // ---- Phase A: scores. warp w owns rows [w*32, w*32+32) ∩ [0,255) ----
    #pragma unroll 4
    for (int i = 0; i < 32; i++) {
        int s = warp * 32 + i;
        if (s >= SM1) break;             // warp-uniform
        const float4* row = (const float4*)(selbase + (size_t)s * DD) + lane * 2;
        float4 a = row[0];
        float4 c = row[1];
        float dot = a.x*qr[0] + a.y*qr[1] + a.z*qr[2] + a.w*qr[3]
                  + c.x*qr[4] + c.y*qr[5] + c.z*qr[6] + c.w*qr[7];
        float ss  = a.x*a.x + a.y*a.y + a.z*a.z + a.w*a.w
                  + c.x*c.x + c.y*c.y + c.z*c.z + c.w*c.w;
        #pragma unroll
        for (int off = 16; off; off >>= 1) {
            dot += __shfl_xor_sync(FULL, dot, off);
            ss  += __shfl_xor_sync(FULL, ss,  off);
        }
        if (lane == 0) {
            bool valid = (s < KK) || (rmb[s] != 0);
            sh_sc[s] = valid ? dot / fmaxf(sqrtf(ss), 1e-12f) : -INFINITY;
        }
    }
    __syncthreads();

    // ---- Phase B: top-32 + softmax on warp 0 ----
    if (warp == 0) {
        float v[8]; int id[8];
        #pragma unroll
        for (int j = 0; j < 8; j++) {
            int idx = lane + 32 * j;
            v[j]  = sh_sc[idx];
            id[j] = idx;
        }
        for (int k = 0; k < KK; k++) {
            float best = -INFINITY; int bidx = 0x7FFFFFFF;
            #pragma unroll
            for (int j = 0; j < 8; j++) {
                if (v[j] > best || (v[j] == best && id[j] < bidx)) {
                    best = v[j]; bidx = id[j];
                }
            }
            #pragma unroll
            for (int off = 16; off; off >>= 1) {
                float ov = __shfl_xor_sync(FULL, best, off);
                int   oi = __shfl_xor_sync(FULL, bidx, off);
                if (ov > best || (ov == best && oi < bidx)) { best = ov; bidx = oi; }
            }
            // all lanes now agree on (best, bidx)
            if (lane == 0) { sh_tv[k] = best; sh_ti[k] = bidx; }
            if (lane == (bidx & 31)) v[bidx >> 5] = -INFINITY;
        }
        __syncwarp();

        // softmax over the 32 (descending) scores; max = sh_tv[0]
        float val = sh_tv[lane];
        float e   = expf(val - sh_tv[0]);
        float ssum = e;
        #pragma unroll
        for (int off = 16; off; off >>= 1) ssum += __shfl_xor_sync(FULL, ssum, off);
        float w = e / ssum;
        sh_w[lane] = w;

        int idx = sh_ti[lane];
        // mask + kid outputs
        out[PS_N + (size_t)bh * KK + lane]        = am[(size_t)bh * SS + 1 + idx];
        out[PS_N + MK_N + (size_t)bh * KK + lane] = (float)idx;
    }
    __syncthreads();

    // ---- Phase C: ps_terms = ne[gather] * w + seg. warp w does rows 4w..4w+3 ----
    const float4 sg0 = ((const float4*)sh_seg)[lane * 2];
    const float4 sg1 = ((const float4*)sh_seg)[lane * 2 + 1];
    #pragma unroll
    for (int r = 0; r < 4; r++) {
        int k = warp * 4 + r;
        float wk = sh_w[k];
        int   idx = sh_ti[k];
        const float4* trow = (const float4*)(ne + ((size_t)bh * SS + 1 + idx) * DD) + lane * 2;
        float4* orow = (float4*)(out + (size_t)bh * KK * DD + (size_t)k * DD) + lane * 2;
        float4 a = trow[0];
        float4 c = trow[1];
        a.x = fmaf(a.x, wk, sg0.x); a.y = fmaf(a.y, wk, sg0.y);
        a.z = fmaf(a.z, wk, sg0.z); a.w = fmaf(a.w, wk, sg0.w);
        c.x = fmaf(c.x, wk, sg1.x); c.y = fmaf(c.y, wk, sg1.y);
        c.z = fmaf(c.z, wk, sg1.z); c.w = fmaf(c.w, wk, sg1.w);
        orow[0] = a;
        orow[1] = c;
    }
}

extern "C" void kernel_launch(void* const* d_in, const int* in_sizes, int n_in,
                              void* d_out, int out_size)
{
    const float* nse  = (const float*)d_in[0];  // news_selection_embedding
    const float* ne   = (const float*)d_in[1];  // news_embedding
    const float* user = (const float*)d_in[2];  // user_repr
    // d_in[3] = news_repr (unused by reference)
    const float* am   = (const float*)d_in[4];  // his_attn_mask
    const int*   rm   = (const int*)  d_in[5];  // his_refined_mask
    const float* seg  = (const float*)d_in[6];  // segment_embedding
    float* out = (float*)d_out;

    qn_kernel<<<BB, 256>>>(user);
    matching_reducer_kernel<<<BB * HH, 256>>>(nse, ne, am, rm, seg, out);
}

// round 2
// speedup vs baseline: 1.2027x; 1.2027x over previous
#include <cuda_runtime.h>
#include <math.h>

#define BB 16
#define HH 50
#define SS 256
#define DD 256
#define KK 32
#define SM1 255           // S-1 candidate rows
#define FULL 0xFFFFFFFFu

// Output layout (tuple flattened, all float32):
//  [0, PS_N)                 ps_terms     (B, H*K, D)
//  [PS_N, PS_N+MK_N)         ps_term_mask (B, H*K)
//  [PS_N+MK_N, PS_N+2*MK_N)  kid          (B, H, K) cast to float
#define PS_N   (BB*HH*KK*DD)
#define MK_N   (BB*HH*KK)

// ---------------------------------------------------------------------------
// One CTA per (b,h). 256 threads = 8 warps.
//   Phase 0: inline q-normalization (user_repr row hits L2 for all CTAs of b)
//   Phase A: warp-per-32-rows cosine scores; 8-row groups with batched LDGs
//            and a SMEM transpose-reduce (no per-row shfl chains)
//   Phase B: warp 0 iterative argmax top-32 (tie-break smaller index),
//            softmax, emit mask + kid
//   Phase C: all warps: weighted gather of news_embedding + segment bias
// ---------------------------------------------------------------------------
__global__ __launch_bounds__(256) void matching_reducer_kernel(
    const float* __restrict__ nse,   // news_selection_embedding (B,H,S,D)
    const float* __restrict__ ne,    // news_embedding           (B,H,S,D)
    const float* __restrict__ user,  // user_repr                (B,1,D)
    const float* __restrict__ am,    // his_attn_mask            (B,H,S)
    const int*   __restrict__ rm,    // his_refined_mask         (B,H,S)
    const float* __restrict__ seg,   // segment_embedding        (H,1,D)
    float*       __restrict__ out)
{
    const int bh = blockIdx.x;       // 0..799
    const int b  = bh / HH;
    const int h  = bh - b * HH;
    const int tid  = threadIdx.x;
    const int lane = tid & 31;
    const int warp = tid >> 5;

    __shared__ float sh_q[DD];
    __shared__ float sh_seg[DD];
    __shared__ float sh_sc[256];
    __shared__ float sh_tv[KK];
    __shared__ int   sh_ti[KK];
    __shared__ float sh_w[KK];
    __shared__ float sh_wsum[8];
    __shared__ unsigned char sh_valid[256];
    __shared__ float sm_red[8][2][8][33];   // [warp][dot/ss][row-in-group][lane]

    // ---- Phase 0: normalize user_repr inline + stage seg & validity ----
    float uv = user[b * DD + tid];
    float ssq = uv * uv;
    #pragma unroll
    for (int off = 16; off; off >>= 1) ssq += __shfl_xor_sync(FULL, ssq, off);
    if (lane == 0) sh_wsum[warp] = ssq;

    if (tid < 64)
        ((float4*)sh_seg)[tid] = ((const float4*)(seg + h * DD))[tid];

    {   // validity of candidate s (original row s+1): keep first K always
        bool v = (tid < KK) || (tid < SM1 && rm[(size_t)bh * SS + 1 + tid] != 0);
        sh_valid[tid] = v ? 1 : 0;
    }
    if (tid == 0) sh_sc[255] = -INFINITY;   // sentinel (slot 255 has no row)
    __syncthreads();

    {
        float tot = 0.f;
        #pragma unroll
        for (int i = 0; i < 8; i++) tot += sh_wsum[i];
        float inv = 1.f / fmaxf(sqrtf(tot), 1e-12f);
        sh_q[tid] = uv * inv;
    }
    __syncthreads();

    float qr[8];
    #pragma unroll
    for (int j = 0; j < 8; j++) qr[j] = sh_q[lane * 8 + j];

    const float* selbase = nse + ((size_t)bh * SS + 1) * DD;

    // ---- Phase A: scores. warp w owns rows [w*32, w*32+32); 4 groups of 8 ----
    #pragma unroll
    for (int g = 0; g < 4; g++) {
        const int s0 = warp * 32 + g * 8;
        float pd[8], ps[8];
        const float4* rp[8];
        #pragma unroll
        for (int j = 0; j < 8; j++) {
            int s = s0 + j;
            int sc = s < (SM1 - 1) ? s : (SM1 - 1);   // clamp row 255 -> safe addr
            rp[j] = (const float4*)(selbase + (size_t)sc * DD) + lane * 2;
        }
        #pragma unroll
        for (int j = 0; j < 8; j++) {
            float4 a = rp[j][0];
            pd[j] = a.x*qr[0] + a.y*qr[1] + a.z*qr[2] + a.w*qr[3];
            ps[j] = a.x*a.x + a.y*a.y + a.z*a.z + a.w*a.w;
        }
        #pragma unroll
        for (int j = 0; j < 8; j++) {
            float4 c = rp[j][1];
            pd[j] += c.x*qr[4] + c.y*qr[5] + c.z*qr[6] + c.w*qr[7];
            ps[j] += c.x*c.x + c.y*c.y + c.z*c.z + c.w*c.w;
        }
        #pragma unroll
        for (int j = 0; j < 8; j++) {
            sm_red[warp][0][j][lane] = pd[j];
            sm_red[warp][1][j][lane] = ps[j];
        }
        __syncwarp();
        {   // lane l reduces quarter (l&3) of row (l>>2); banks conflict-free
            int j = lane >> 2, q = lane & 3;
            float dsum = 0.f, ssum = 0.f;
            #pragma unroll
            for (int t = 0; t < 8; t++) {
                dsum += sm_red[warp][0][j][q * 8 + t];
                ssum += sm_red[warp][1][j][q * 8 + t];
            }
            dsum += __shfl_xor_sync(FULL, dsum, 1);
            ssum += __shfl_xor_sync(FULL, ssum, 1);
            dsum += __shfl_xor_sync(FULL, dsum, 2);
            ssum += __shfl_xor_sync(FULL, ssum, 2);
            int s = s0 + j;
            if (q == 0) {
                float sc;
                if (s < SM1 && sh_valid[s])
                    sc = dsum / fmaxf(sqrtf(ssum), 1e-12f);
                else
                    sc = -INFINITY;
                sh_sc[s] = sc;
            }
        }
        __syncwarp();   // protect sm_red reuse next group
    }
    __syncthreads();

    // ---- Phase B: top-32 + softmax on warp 0 ----
    if (warp == 0) {
        float v[8]; int id[8];
        #pragma unroll
        for (int j = 0; j < 8; j++) {
            int idx = lane + 32 * j;
            v[j]  = sh_sc[idx];
            id[j] = idx;
        }
        for (int k = 0; k < KK; k++) {
            float best = -INFINITY; int bidx = 0x7FFFFFFF;
            #pragma unroll
            for (int j = 0; j < 8; j++) {
                if (v[j] > best || (v[j] == best && id[j] < bidx)) {
                    best = v[j]; bidx = id[j];
                }
            }
            #pragma unroll
            for (int off = 16; off; off >>= 1) {
                float ov = __shfl_xor_sync(FULL, best, off);
                int   oi = __shfl_xor_sync(FULL, bidx, off);
                if (ov > best || (ov == best && oi < bidx)) { best = ov; bidx = oi; }
            }
            if (lane == 0) { sh_tv[k] = best; sh_ti[k] = bidx; }
            if (lane == (bidx & 31)) v[bidx >> 5] = -INFINITY;
        }
        __syncwarp();

        float val = sh_tv[lane];
        float e   = expf(val - sh_tv[0]);
        float esum = e;
        #pragma unroll
        for (int off = 16; off; off >>= 1) esum += __shfl_xor_sync(FULL, esum, off);
        float w = e / esum;
        sh_w[lane] = w;

        int idx = sh_ti[lane];
        out[PS_N + (size_t)bh * KK + lane]        = am[(size_t)bh * SS + 1 + idx];
        out[PS_N + MK_N + (size_t)bh * KK + lane] = (float)idx;
    }
    __syncthreads();

    // ---- Phase C: ps_terms = ne[gather] * w + seg. warp w does rows 4w..4w+3 ----
    const float4 sg0 = ((const float4*)sh_seg)[lane * 2];
    const float4 sg1 = ((const float4*)sh_seg)[lane * 2 + 1];
    #pragma unroll
    for (int r = 0; r < 4; r++) {
        int k = warp * 4 + r;
        float wk = sh_w[k];
        int   idx = sh_ti[k];
        const float4* trow = (const float4*)(ne + ((size_t)bh * SS + 1 + idx) * DD) + lane * 2;
        float4* orow = (float4*)(out + (size_t)bh * KK * DD + (size_t)k * DD) + lane * 2;
        float4 a = trow[0];
        float4 c = trow[1];
        a.x = fmaf(a.x, wk, sg0.x); a.y = fmaf(a.y, wk, sg0.y);
        a.z = fmaf(a.z, wk, sg0.z); a.w = fmaf(a.w, wk, sg0.w);
        c.x = fmaf(c.x, wk, sg1.x); c.y = fmaf(c.y, wk, sg1.y);
        c.z = fmaf(c.z, wk, sg1.z); c.w = fmaf(c.w, wk, sg1.w);
        orow[0] = a;
        orow[1] = c;
    }
}

extern "C" void kernel_launch(void* const* d_in, const int* in_sizes, int n_in,
                              void* d_out, int out_size)
{
    const float* nse  = (const float*)d_in[0];  // news_selection_embedding
    const float* ne   = (const float*)d_in[1];  // news_embedding
    const float* user = (const float*)d_in[2];  // user_repr
    // d_in[3] = news_repr (unused by reference)
    const float* am   = (const float*)d_in[4];  // his_attn_mask
    const int*   rm   = (const int*)  d_in[5];  // his_refined_mask
    const float* seg  = (const float*)d_in[6];  // segment_embedding
    float* out = (float*)d_out;

    matching_reducer_kernel<<<BB * HH, 256>>>(nse, ne, user, am, rm, seg, out);
}

// round 3
// speedup vs baseline: 1.4241x; 1.1840x over previous
#include <cuda_runtime.h>
#include <math.h>

#define BB 16
#define HH 50
#define SS 256
#define DD 256
#define KK 32
#define SM1 255           // S-1 candidate rows
#define FULL 0xFFFFFFFFu

// Output layout (tuple flattened, all float32):
//  [0, PS_N)                 ps_terms     (B, H*K, D)
//  [PS_N, PS_N+MK_N)         ps_term_mask (B, H*K)
//  [PS_N+MK_N, PS_N+2*MK_N)  kid          (B, H, K) cast to float
#define PS_N   (BB*HH*KK*DD)
#define MK_N   (BB*HH*KK)

// ---------------------------------------------------------------------------
// One CTA per (b,h). 256 threads = 8 warps.
//   Phase 0: inline q-normalization
//   Phase A: warp-per-32-rows; 8 groups of 4 rows, DOUBLE-BUFFERED so the
//            next group's 8 LDG.128 issue before this group's FMAs consume.
//            SMEM transpose-reduce (no long shfl chains).
//   Phase B: warp 0 iterative argmax top-32 (tie-break smaller index),
//            softmax, emit mask + kid
//   Phase C: weighted gather of news_embedding + segment bias (batched loads)
// ---------------------------------------------------------------------------
__global__ __launch_bounds__(256) void matching_reducer_kernel(
    const float* __restrict__ nse,   // news_selection_embedding (B,H,S,D)
    const float* __restrict__ ne,    // news_embedding           (B,H,S,D)
    const float* __restrict__ user,  // user_repr                (B,1,D)
    const float* __restrict__ am,    // his_attn_mask            (B,H,S)
    const int*   __restrict__ rm,    // his_refined_mask         (B,H,S)
    const float* __restrict__ seg,   // segment_embedding        (H,1,D)
    float*       __restrict__ out)
{
    const int bh = blockIdx.x;       // 0..799
    const int b  = bh / HH;
    const int h  = bh - b * HH;
    const int tid  = threadIdx.x;
    const int lane = tid & 31;
    const int warp = tid >> 5;

    __shared__ float sh_q[DD];
    __shared__ float sh_seg[DD];
    __shared__ float sh_sc[256];
    __shared__ float sh_tv[KK];
    __shared__ int   sh_ti[KK];
    __shared__ float sh_w[KK];
    __shared__ float sh_wsum[8];
    __shared__ unsigned char sh_valid[256];
    __shared__ float sm_red[8][2][4][33];   // [warp][dot/ss][row-in-group][lane]

    // ---- Phase 0: normalize user_repr inline + stage seg & validity ----
    float uv = user[b * DD + tid];
    float ssq = uv * uv;
    #pragma unroll
    for (int off = 16; off; off >>= 1) ssq += __shfl_xor_sync(FULL, ssq, off);
    if (lane == 0) sh_wsum[warp] = ssq;

    if (tid < 64)
        ((float4*)sh_seg)[tid] = ((const float4*)(seg + h * DD))[tid];

    {   // validity of candidate s (original row s+1): keep first K always
        bool v = (tid < KK) || (tid < SM1 && rm[(size_t)bh * SS + 1 + tid] != 0);
        sh_valid[tid] = v ? 1 : 0;
    }
    __syncthreads();

    {
        float tot = 0.f;
        #pragma unroll
        for (int i = 0; i < 8; i++) tot += sh_wsum[i];
        float inv = 1.f / fmaxf(sqrtf(tot), 1e-12f);
        sh_q[tid] = uv * inv;
    }
    __syncthreads();

    float qr[8];
    #pragma unroll
    for (int j = 0; j < 8; j++) qr[j] = sh_q[lane * 8 + j];

    const float* selbase = nse + ((size_t)bh * SS + 1) * DD;
    const int rbase = warp * 32;

    // ---- Phase A: 8 groups x 4 rows, double-buffered ----
    float4 va[2][4], vc[2][4];

    #pragma unroll
    for (int j = 0; j < 4; j++) {                 // prefetch group 0
        int s = rbase + j;
        const float4* p = (const float4*)(selbase + (size_t)s * DD) + lane * 2;
        va[0][j] = __ldcs(p);
        vc[0][j] = __ldcs(p + 1);
    }

    #pragma unroll
    for (int g = 0; g < 8; g++) {
        const int buf = g & 1;
        if (g < 7) {                              // issue next group's loads FIRST
            #pragma unroll
            for (int j = 0; j < 4; j++) {
                int s = rbase + (g + 1) * 4 + j;
                int scl = s < SM1 ? s : (SM1 - 1);   // clamp sentinel row 255
                const float4* p = (const float4*)(selbase + (size_t)scl * DD) + lane * 2;
                va[buf ^ 1][j] = __ldcs(p);
                vc[buf ^ 1][j] = __ldcs(p + 1);
            }
        }
        float pd[4], ps[4];
        #pragma unroll
        for (int j = 0; j < 4; j++) {
            float4 a = va[buf][j], c = vc[buf][j];
            pd[j] = a.x*qr[0] + a.y*qr[1] + a.z*qr[2] + a.w*qr[3]
                  + c.x*qr[4] + c.y*qr[5] + c.z*qr[6] + c.w*qr[7];
            ps[j] = a.x*a.x + a.y*a.y + a.z*a.z + a.w*a.w
                  + c.x*c.x + c.y*c.y + c.z*c.z + c.w*c.w;
        }
        #pragma unroll
        for (int j = 0; j < 4; j++) {
            sm_red[warp][0][j][lane] = pd[j];
            sm_red[warp][1][j][lane] = ps[j];
        }
        __syncwarp();
        {   // lane: row j = lane>>3, eighth q = lane&7 (4 elems each) -> 3 shfls
            int j = lane >> 3, q = lane & 7;
            float dsum = 0.f, ssum = 0.f;
            #pragma unroll
            for (int t = 0; t < 4; t++) {
                dsum += sm_red[warp][0][j][q * 4 + t];
                ssum += sm_red[warp][1][j][q * 4 + t];
            }
            #pragma unroll
            for (int off = 1; off <= 4; off <<= 1) {
                dsum += __shfl_xor_sync(FULL, dsum, off);
                ssum += __shfl_xor_sync(FULL, ssum, off);
            }
            int s = rbase + g * 4 + j;
            if (q == 0) {
                float sc;
                if (sh_valid[s])                  // s==255 -> invalid -> -inf
                    sc = dsum / fmaxf(sqrtf(ssum), 1e-12f);
                else
                    sc = -INFINITY;
                sh_sc[s] = sc;
            }
        }
        __syncwarp();   // protect sm_red reuse next group
    }
    __syncthreads();

    // ---- Phase B: top-32 + softmax on warp 0 ----
    if (warp == 0) {
        float v[8]; int id[8];
        #pragma unroll
        for (int j = 0; j < 8; j++) {
            int idx = lane + 32 * j;
            v[j]  = sh_sc[idx];
            id[j] = idx;
        }
        for (int k = 0; k < KK; k++) {
            float best = -INFINITY; int bidx = 0x7FFFFFFF;
            #pragma unroll
            for (int j = 0; j < 8; j++) {
                if (v[j] > best || (v[j] == best && id[j] < bidx)) {
                    best = v[j]; bidx = id[j];
                }
            }
            #pragma unroll
            for (int off = 16; off; off >>= 1) {
                float ov = __shfl_xor_sync(FULL, best, off);
                int   oi = __shfl_xor_sync(FULL, bidx, off);
                if (ov > best || (ov == best && oi < bidx)) { best = ov; bidx = oi; }
            }
            if (lane == 0) { sh_tv[k] = best; sh_ti[k] = bidx; }
            if (lane == (bidx & 31)) v[bidx >> 5] = -INFINITY;
        }
        __syncwarp();

        float val = sh_tv[lane];
        float e   = expf(val - sh_tv[0]);
        float esum = e;
        #pragma unroll
        for (int off = 16; off; off >>= 1) esum += __shfl_xor_sync(FULL, esum, off);
        float w = e / esum;
        sh_w[lane] = w;

        int idx = sh_ti[lane];
        out[PS_N + (size_t)bh * KK + lane]        = am[(size_t)bh * SS + 1 + idx];
        out[PS_N + MK_N + (size_t)bh * KK + lane] = (float)idx;
    }
    __syncthreads();

    // ---- Phase C: ps_terms = ne[gather]*w + seg. Warp does 4 rows, batched ----
    const float4 sg0 = ((const float4*)sh_seg)[lane * 2];
    const float4 sg1 = ((const float4*)sh_seg)[lane * 2 + 1];
    float4 ta[4], tc[4];
    float  wk[4];
    int    ki[4];
    #pragma unroll
    for (int r = 0; r < 4; r++) {
        int k = warp * 4 + r;
        wk[r] = sh_w[k];
        ki[r] = sh_ti[k];
    }
    #pragma unroll
    for (int r = 0; r < 4; r++) {
        const float4* trow = (const float4*)(ne + ((size_t)bh * SS + 1 + ki[r]) * DD) + lane * 2;
        ta[r] = __ldcs(trow);
        tc[r] = __ldcs(trow + 1);
    }
    #pragma unroll
    for (int r = 0; r < 4; r++) {
        int k = warp * 4 + r;
        float4 a = ta[r], c = tc[r];
        a.x = fmaf(a.x, wk[r], sg0.x); a.y = fmaf(a.y, wk[r], sg0.y);
        a.z = fmaf(a.z, wk[r], sg0.z); a.w = fmaf(a.w, wk[r], sg0.w);
        c.x = fmaf(c.x, wk[r], sg1.x); c.y = fmaf(c.y, wk[r], sg1.y);
        c.z = fmaf(c.z, wk[r], sg1.z); c.w = fmaf(c.w, wk[r], sg1.w);
        float4* orow = (float4*)(out + (size_t)bh * KK * DD + (size_t)k * DD) + lane * 2;
        __stcs(orow, a);
        __stcs(orow + 1, c);
    }
}

extern "C" void kernel_launch(void* const* d_in, const int* in_sizes, int n_in,
                              void* d_out, int out_size)
{
    const float* nse  = (const float*)d_in[0];  // news_selection_embedding
    const float* ne   = (const float*)d_in[1];  // news_embedding
    const float* user = (const float*)d_in[2];  // user_repr
    // d_in[3] = news_repr (unused by reference)
    const float* am   = (const float*)d_in[4];  // his_attn_mask
    const int*   rm   = (const int*)  d_in[5];  // his_refined_mask
    const float* seg  = (const float*)d_in[6];  // segment_embedding
    float* out = (float*)d_out;

    matching_reducer_kernel<<<BB * HH, 256>>>(nse, ne, user, am, rm, seg, out);
}